// round 1
// baseline (speedup 1.0000x reference)
#include <cuda_runtime.h>
#include <math.h>

#define B_ 4
#define L_ 1024
#define H_ 8
#define D_ 64
#define BH_ 32
#define INV_TEMP 0.125f

#define TM 32     // query rows per CTA
#define KT 128    // key/value tile rows

// scratch: normalized q/k and transposed v in [BH, L, D] layout (8 MB each)
__device__ float g_qn[BH_ * L_ * D_];
__device__ float g_kn[BH_ * L_ * D_];
__device__ float g_vt[BH_ * L_ * D_];

__device__ __forceinline__ float warp_sum(float s) {
#pragma unroll
    for (int o = 16; o > 0; o >>= 1) s += __shfl_xor_sync(0xffffffffu, s, o);
    return s;
}
__device__ __forceinline__ float warp_max(float s) {
#pragma unroll
    for (int o = 16; o > 0; o >>= 1) s = fmaxf(s, __shfl_xor_sync(0xffffffffu, s, o));
    return s;
}

// One warp per (b, l, h) row: L2-normalize q,k; copy v; all into [BH, L, D].
__global__ void norm_transpose_kernel(const float* __restrict__ q,
                                      const float* __restrict__ k,
                                      const float* __restrict__ v) {
    int warp = (blockIdx.x * blockDim.x + threadIdx.x) >> 5;
    int lane = threadIdx.x & 31;
    if (warp >= B_ * L_ * H_) return;
    int b = warp / (L_ * H_);
    int rem = warp % (L_ * H_);
    int l = rem / H_;
    int h = rem % H_;
    long src = (((long)b * L_ + l) * H_ + h) * D_ + 2 * lane;
    long dst = (((long)b * H_ + h) * L_ + l) * D_ + 2 * lane;

    float2 qv = *(const float2*)(q + src);
    float s = warp_sum(qv.x * qv.x + qv.y * qv.y);
    float sc = 1.0f / fmaxf(sqrtf(s), 1e-8f);
    qv.x *= sc; qv.y *= sc;
    *(float2*)(g_qn + dst) = qv;

    float2 kv = *(const float2*)(k + src);
    s = warp_sum(kv.x * kv.x + kv.y * kv.y);
    sc = 1.0f / fmaxf(sqrtf(s), 1e-8f);
    kv.x *= sc; kv.y *= sc;
    *(float2*)(g_kn + dst) = kv;

    *(float2*)(g_vt + dst) = *(const float2*)(v + src);
}

// SMEM layout (floats): sS[TM*L] | sQ[TM*D] | sKV[KT*D]
#define SMEM_FLOATS (TM * L_ + TM * D_ + KT * D_)

__global__ __launch_bounds__(256, 1)
void attn_kernel(float* __restrict__ outp, float* __restrict__ attnp) {
    extern __shared__ float smem[];
    float* sS  = smem;
    float* sQ  = smem + TM * L_;
    float* sKV = sQ + TM * D_;

    const int t  = threadIdx.x;
    const int tx = t & 31;
    const int ty = t >> 5;          // warp id, 0..7
    const int bh = blockIdx.y;
    const int q0 = blockIdx.x * TM;

    const float* Qg = g_qn + ((long)bh * L_ + q0) * D_;
    const float* Kg = g_kn + (long)bh * L_ * D_;
    const float* Vg = g_vt + (long)bh * L_ * D_;

    // ---- load Q tile (contiguous TM*D floats) ----
    {
        const float4* src = (const float4*)Qg;
        float4* d4 = (float4*)sQ;
#pragma unroll
        for (int i = t; i < TM * D_ / 4; i += 256) d4[i] = src[i];
    }

    // ---- phase 1: S = Qn Kn^T / TEMP into sS ----
    for (int kt = 0; kt < L_ / KT; kt++) {
        __syncthreads();
        // load K tile with XOR swizzle: row r, f4-col f -> slot r*16 + (f ^ (r&15))
        {
            const float4* src = (const float4*)(Kg + kt * KT * D_);
            float4* d4 = (float4*)sKV;
#pragma unroll
            for (int i = 0; i < (KT * D_ / 4) / 256; i++) {
                int i4 = t + 256 * i;
                int r = i4 >> 4, f = i4 & 15;
                d4[(r << 4) | (f ^ (r & 15))] = src[i4];
            }
        }
        __syncthreads();

        float acc[4][4];
#pragma unroll
        for (int r = 0; r < 4; r++)
#pragma unroll
            for (int c = 0; c < 4; c++) acc[r][c] = 0.0f;

        const float4* q4 = (const float4*)sQ;
        const float4* k4 = (const float4*)sKV;
#pragma unroll
        for (int f = 0; f < 16; f++) {
            float4 qv[4], kv[4];
#pragma unroll
            for (int r = 0; r < 4; r++) qv[r] = q4[(ty * 4 + r) * 16 + f];
            int fs = f ^ (tx & 15);
#pragma unroll
            for (int c = 0; c < 4; c++) kv[c] = k4[((tx + 32 * c) << 4) + fs];
#pragma unroll
            for (int r = 0; r < 4; r++)
#pragma unroll
                for (int c = 0; c < 4; c++) {
                    acc[r][c] += qv[r].x * kv[c].x;
                    acc[r][c] += qv[r].y * kv[c].y;
                    acc[r][c] += qv[r].z * kv[c].z;
                    acc[r][c] += qv[r].w * kv[c].w;
                }
        }
#pragma unroll
        for (int r = 0; r < 4; r++)
#pragma unroll
            for (int c = 0; c < 4; c++)
                sS[(ty * 4 + r) * L_ + kt * KT + tx + 32 * c] = acc[r][c] * INV_TEMP;
    }
    __syncthreads();

    // ---- phase 2: row softmax; write normalized attn to gmem and back to sS ----
    {
#pragma unroll
        for (int rr = 0; rr < 4; rr++) {
            int row = ty * 4 + rr;
            float4* srow4 = (float4*)(sS + row * L_);
            float4* arow4 = (float4*)(attnp + ((long)bh * L_ + q0 + row) * L_);

            float4 ev[8];
            float m = -1e30f;
#pragma unroll
            for (int i = 0; i < 8; i++) {
                ev[i] = srow4[tx + 32 * i];
                m = fmaxf(m, fmaxf(fmaxf(ev[i].x, ev[i].y), fmaxf(ev[i].z, ev[i].w)));
            }
            m = warp_max(m);
            float ssum = 0.0f;
#pragma unroll
            for (int i = 0; i < 8; i++) {
                ev[i].x = __expf(ev[i].x - m);
                ev[i].y = __expf(ev[i].y - m);
                ev[i].z = __expf(ev[i].z - m);
                ev[i].w = __expf(ev[i].w - m);
                ssum += ev[i].x + ev[i].y + ev[i].z + ev[i].w;
            }
            ssum = warp_sum(ssum);
            float inv = 1.0f / ssum;
#pragma unroll
            for (int i = 0; i < 8; i++) {
                ev[i].x *= inv; ev[i].y *= inv; ev[i].z *= inv; ev[i].w *= inv;
                srow4[tx + 32 * i] = ev[i];
                arow4[tx + 32 * i] = ev[i];
            }
        }
    }
    __syncthreads();

    // ---- phase 3: O = P @ V ----
    float oacc[4][2];
#pragma unroll
    for (int r = 0; r < 4; r++) { oacc[r][0] = 0.0f; oacc[r][1] = 0.0f; }

    const float4* s4 = (const float4*)sS;
    for (int vt = 0; vt < L_ / KT; vt++) {
        // load V tile (linear layout)
        {
            const float4* src = (const float4*)(Vg + vt * KT * D_);
            float4* d4 = (float4*)sKV;
#pragma unroll
            for (int i = 0; i < (KT * D_ / 4) / 256; i++) d4[t + 256 * i] = src[t + 256 * i];
        }
        __syncthreads();

#pragma unroll 4
        for (int jb = 0; jb < KT / 4; jb++) {
            float4 p[4];
#pragma unroll
            for (int r = 0; r < 4; r++)
                p[r] = s4[(ty * 4 + r) * (L_ / 4) + vt * (KT / 4) + jb];
#pragma unroll
            for (int jj = 0; jj < 4; jj++) {
                float v0 = sKV[(jb * 4 + jj) * D_ + tx];
                float v1 = sKV[(jb * 4 + jj) * D_ + tx + 32];
#pragma unroll
                for (int r = 0; r < 4; r++) {
                    float pv = (jj == 0) ? p[r].x : (jj == 1) ? p[r].y : (jj == 2) ? p[r].z : p[r].w;
                    oacc[r][0] += pv * v0;
                    oacc[r][1] += pv * v1;
                }
            }
        }
        __syncthreads();  // before next tile overwrites sKV
    }

#pragma unroll
    for (int r = 0; r < 4; r++) {
        long orow = ((long)bh * L_ + q0 + ty * 4 + r) * D_;
        outp[orow + tx]      = oacc[r][0];
        outp[orow + tx + 32] = oacc[r][1];
    }
}

extern "C" void kernel_launch(void* const* d_in, const int* in_sizes, int n_in,
                              void* d_out, int out_size) {
    const float* q = (const float*)d_in[0];
    const float* k = (const float*)d_in[1];
    const float* v = (const float*)d_in[2];
    float* outp  = (float*)d_out;                       // [B,H,L,D]
    float* attnp = outp + (long)BH_ * L_ * D_;          // [B,H,L,L]

    // normalize + transpose: one warp per (b,l,h) row
    int rows = B_ * L_ * H_;
    norm_transpose_kernel<<<rows / 8, 256>>>(q, k, v);

    size_t smem_bytes = (size_t)SMEM_FLOATS * sizeof(float);  // 172,032 B
    cudaFuncSetAttribute(attn_kernel, cudaFuncAttributeMaxDynamicSharedMemorySize,
                         (int)smem_bytes);
    dim3 grid(L_ / TM, BH_);
    attn_kernel<<<grid, 256, smem_bytes>>>(outp, attnp);
}

// round 5
// speedup vs baseline: 2.4001x; 2.4001x over previous
#include <cuda_runtime.h>
#include <cuda_fp16.h>
#include <stdint.h>
#include <math.h>

#define B_ 4
#define L_ 1024
#define H_ 8
#define D_ 64
#define BH_ 32
#define INV_TEMP 0.125f
#define TM 32
#define KC 128

typedef unsigned int u32;

__device__ __align__(16) __half g_qh[BH_ * L_ * D_];
__device__ __align__(16) __half g_kh[BH_ * L_ * D_];
__device__ __align__(16) __half g_vh[BH_ * L_ * D_];

__device__ __forceinline__ float warp_sum(float s) {
#pragma unroll
    for (int o = 16; o > 0; o >>= 1) s += __shfl_xor_sync(0xffffffffu, s, o);
    return s;
}
__device__ __forceinline__ float warp_max(float s) {
#pragma unroll
    for (int o = 16; o > 0; o >>= 1) s = fmaxf(s, __shfl_xor_sync(0xffffffffu, s, o));
    return s;
}

__device__ __forceinline__ void ldsm4(u32 addr, u32* r) {
    asm volatile("ldmatrix.sync.aligned.m8n8.x4.shared.b16 {%0,%1,%2,%3}, [%4];"
                 : "=r"(r[0]), "=r"(r[1]), "=r"(r[2]), "=r"(r[3]) : "r"(addr));
}
__device__ __forceinline__ void ldsm4t(u32 addr, u32* r) {
    asm volatile("ldmatrix.sync.aligned.m8n8.x4.trans.shared.b16 {%0,%1,%2,%3}, [%4];"
                 : "=r"(r[0]), "=r"(r[1]), "=r"(r[2]), "=r"(r[3]) : "r"(addr));
}
__device__ __forceinline__ void hmma(float* c, const u32* a, u32 b0, u32 b1) {
    asm volatile(
        "mma.sync.aligned.m16n8k16.row.col.f32.f16.f16.f32 "
        "{%0,%1,%2,%3}, {%4,%5,%6,%7}, {%8,%9}, {%0,%1,%2,%3};"
        : "+f"(c[0]), "+f"(c[1]), "+f"(c[2]), "+f"(c[3])
        : "r"(a[0]), "r"(a[1]), "r"(a[2]), "r"(a[3]), "r"(b0), "r"(b1));
}

__global__ void prep_kernel(const float* __restrict__ q,
                            const float* __restrict__ k,
                            const float* __restrict__ v) {
    const int warp = (blockIdx.x * blockDim.x + threadIdx.x) >> 5;
    const int lane = threadIdx.x & 31;
    const int b = warp / (L_ * H_);
    const int rem = warp % (L_ * H_);
    const int l = rem / H_;
    const int h = rem % H_;
    const long src = (((long)b * L_ + l) * H_ + h) * D_ + 2 * lane;
    const long dst = (((long)b * H_ + h) * L_ + l) * D_ + 2 * lane;

    float2 qv = *(const float2*)(q + src);
    float s = warp_sum(qv.x * qv.x + qv.y * qv.y);
    float sc = 1.0f / fmaxf(sqrtf(s), 1e-8f);
    *(half2*)(g_qh + dst) = __floats2half2_rn(qv.x * sc, qv.y * sc);

    float2 kv = *(const float2*)(k + src);
    s = warp_sum(kv.x * kv.x + kv.y * kv.y);
    sc = 1.0f / fmaxf(sqrtf(s), 1e-8f);
    *(half2*)(g_kh + dst) = __floats2half2_rn(kv.x * sc, kv.y * sc);

    float2 vv = *(const float2*)(v + src);
    *(half2*)(g_vh + dst) = __floats2half2_rn(vv.x, vv.y);
}

// SMEM: sS f32[32][1024] @0 (131072B, row-swizzled by 16B chunk)
//       sP f16[32][1024] @131072 (65536B, swizzled)
//       sQ f16[32][64]   @196608 (4096B, swizzled)
//       sKV f16[128][64] @200704 (16384B, swizzled)
#define SP_OFF  131072
#define SQ_OFF  196608
#define SKV_OFF 200704
#define SMEM_BYTES 217088

__global__ __launch_bounds__(256, 1)
void attn_kernel(float* __restrict__ outp, float* __restrict__ attnp) {
    extern __shared__ char smem[];
    float* sS = (float*)smem;
    const u32 sbase = (u32)__cvta_generic_to_shared(smem);
    const u32 sPu = sbase + SP_OFF;
    const u32 sQu = sbase + SQ_OFF;
    const u32 sKVu = sbase + SKV_OFF;

    const int t = threadIdx.x;
    const int tx = t & 31;
    const int ty = t >> 5;
    const int wm = ty & 1;
    const int wn = ty >> 1;
    const int bh = blockIdx.y;
    const int q0 = blockIdx.x * TM;
    const int lg = tx >> 2;
    const int ltg = tx & 3;
    const int lm = tx >> 3;
    const int lr = tx & 7;

    const __half* Qg = g_qh + ((long)bh * L_ + q0) * D_;
    const __half* Kg = g_kh + (long)bh * L_ * D_;
    const __half* Vg = g_vh + (long)bh * L_ * D_;

    u32 fa[4];
    u32 fb[4];

    // ---- Q tile load (32x64 f16), swizzled ----
    {
        const uint4* src = (const uint4*)Qg;
        uint4* dst = (uint4*)(smem + SQ_OFF);
        const int row = t >> 3;
        const int ch = t & 7;
        dst[(row << 3) | (ch ^ (row & 7))] = src[t];
    }

    // ================= phase 1: S = Qn Kn^T * INV_TEMP =================
    for (int kt = 0; kt < L_ / KC; kt++) {
        __syncthreads();
        {
            const uint4* src = (const uint4*)(Kg + (size_t)kt * KC * D_);
            uint4* dst = (uint4*)(smem + SKV_OFF);
#pragma unroll
            for (int i = 0; i < 4; i++) {
                const int idx = t + 256 * i;
                const int row = idx >> 3;
                const int ch = idx & 7;
                dst[(row << 3) | (ch ^ (row & 7))] = src[idx];
            }
        }
        __syncthreads();

        float c[4][4];
#pragma unroll
        for (int nt = 0; nt < 4; nt++) {
            c[nt][0] = 0.0f; c[nt][1] = 0.0f; c[nt][2] = 0.0f; c[nt][3] = 0.0f;
        }

#pragma unroll
        for (int kk = 0; kk < 4; kk++) {
            const int arow = 16 * wm + (lm & 1) * 8 + lr;
            const int ach = 2 * kk + (lm >> 1);
            ldsm4(sQu + arow * 128 + ((ach ^ (arow & 7)) << 4), fa);
#pragma unroll
            for (int p = 0; p < 2; p++) {
                const int brow = wn * 32 + p * 16 + (lm >> 1) * 8 + lr;
                const int bch = 2 * kk + (lm & 1);
                ldsm4(sKVu + brow * 128 + ((bch ^ (brow & 7)) << 4), fb);
                hmma(c[2 * p], fa, fb[0], fb[1]);
                hmma(c[2 * p + 1], fa, fb[2], fb[3]);
            }
        }
#pragma unroll
        for (int nt = 0; nt < 4; nt++) {
            const int col = kt * KC + wn * 32 + nt * 8 + 2 * ltg;
            const int r0 = 16 * wm + lg;
            const int r1 = r0 + 8;
            const int i0 = r0 * 1024 + (((col >> 2) ^ (r0 & 7)) << 2) + (col & 3);
            const int i1 = r1 * 1024 + (((col >> 2) ^ (r1 & 7)) << 2) + (col & 3);
            *(float2*)(sS + i0) = make_float2(c[nt][0] * INV_TEMP, c[nt][1] * INV_TEMP);
            *(float2*)(sS + i1) = make_float2(c[nt][2] * INV_TEMP, c[nt][3] * INV_TEMP);
        }
    }
    __syncthreads();

    // ============ phase 2: softmax rows -> attn gmem + f16 sP ============
#pragma unroll
    for (int rr = 0; rr < 4; rr++) {
        const int row = ty * 4 + rr;
        const float4* s4 = (const float4*)sS;
        float4* arow4 = (float4*)(attnp + ((long)bh * L_ + q0 + row) * L_);

        float4 ev[8];
        float m = -1e30f;
#pragma unroll
        for (int i = 0; i < 8; i++) {
            ev[i] = s4[row * 256 + ((tx + 32 * i) ^ (row & 7))];
            m = fmaxf(m, fmaxf(fmaxf(ev[i].x, ev[i].y), fmaxf(ev[i].z, ev[i].w)));
        }
        m = warp_max(m);
        float ssum = 0.0f;
#pragma unroll
        for (int i = 0; i < 8; i++) {
            ev[i].x = __expf(ev[i].x - m);
            ev[i].y = __expf(ev[i].y - m);
            ev[i].z = __expf(ev[i].z - m);
            ev[i].w = __expf(ev[i].w - m);
            ssum += ev[i].x + ev[i].y + ev[i].z + ev[i].w;
        }
        ssum = warp_sum(ssum);
        const float inv = 1.0f / ssum;
#pragma unroll
        for (int i = 0; i < 8; i++) {
            ev[i].x *= inv; ev[i].y *= inv; ev[i].z *= inv; ev[i].w *= inv;
            arow4[tx + 32 * i] = ev[i];
            const int c4 = tx + 32 * i;
            char* pa = smem + SP_OFF + row * 2048 +
                       (((c4 >> 1) ^ (row & 7)) << 4) + (c4 & 1) * 8;
            *(half2*)pa       = __floats2half2_rn(ev[i].x, ev[i].y);
            *(half2*)(pa + 4) = __floats2half2_rn(ev[i].z, ev[i].w);
        }
    }
    __syncthreads();

    // ================= phase 3: O = P @ V =================
    float oc0[4];
    float oc1[4];
    oc0[0] = oc0[1] = oc0[2] = oc0[3] = 0.0f;
    oc1[0] = oc1[1] = oc1[2] = oc1[3] = 0.0f;

    for (int vc = 0; vc < L_ / KC; vc++) {
        __syncthreads();
        {
            const uint4* src = (const uint4*)(Vg + (size_t)vc * KC * D_);
            uint4* dst = (uint4*)(smem + SKV_OFF);
#pragma unroll
            for (int i = 0; i < 4; i++) {
                const int idx = t + 256 * i;
                const int row = idx >> 3;
                const int ch = idx & 7;
                dst[(row << 3) | (ch ^ (row & 7))] = src[idx];
            }
        }
        __syncthreads();

#pragma unroll
        for (int kk = 0; kk < 8; kk++) {
            const int arow = 16 * wm + (lm & 1) * 8 + lr;
            const int ach = vc * 16 + 2 * kk + (lm >> 1);
            ldsm4(sPu + arow * 2048 + ((ach ^ (arow & 7)) << 4), fa);

            const int srow = kk * 16 + (lm & 1) * 8 + lr;
            const int sch = wn * 2 + (lm >> 1);
            ldsm4t(sKVu + srow * 128 + ((sch ^ (srow & 7)) << 4), fb);

            hmma(oc0, fa, fb[0], fb[1]);
            hmma(oc1, fa, fb[2], fb[3]);
        }
    }

    // ---- epilogue ----
    {
        const int d0 = wn * 16 + 2 * ltg;
        const long base0 = ((long)bh * L_ + q0 + 16 * wm + lg) * D_ + d0;
        *(float2*)(outp + base0)           = make_float2(oc0[0], oc0[1]);
        *(float2*)(outp + base0 + 8 * D_)  = make_float2(oc0[2], oc0[3]);
        const long base1 = base0 + 8;
        *(float2*)(outp + base1)           = make_float2(oc1[0], oc1[1]);
        *(float2*)(outp + base1 + 8 * D_)  = make_float2(oc1[2], oc1[3]);
    }
}

extern "C" void kernel_launch(void* const* d_in, const int* in_sizes, int n_in,
                              void* d_out, int out_size) {
    const float* q = (const float*)d_in[0];
    const float* k = (const float*)d_in[1];
    const float* v = (const float*)d_in[2];
    float* outp  = (float*)d_out;
    float* attnp = outp + (long)BH_ * L_ * D_;

    prep_kernel<<<(B_ * L_ * H_) / 8, 256>>>(q, k, v);

    cudaFuncSetAttribute(attn_kernel, cudaFuncAttributeMaxDynamicSharedMemorySize,
                         SMEM_BYTES);
    dim3 grid(L_ / TM, BH_);
    attn_kernel<<<grid, 256, SMEM_BYTES>>>(outp, attnp);
}

// round 6
// speedup vs baseline: 4.0561x; 1.6899x over previous
#include <cuda_runtime.h>
#include <cuda_fp16.h>
#include <stdint.h>
#include <math.h>

#define B_ 4
#define L_ 1024
#define H_ 8
#define D_ 64
#define BH_ 32
#define INV_TEMP 0.125f
#define TM 32
#define KC 128

typedef unsigned int u32;

__device__ __align__(16) __half g_qh[BH_ * L_ * D_];
__device__ __align__(16) __half g_kh[BH_ * L_ * D_];
__device__ __align__(16) __half g_vh[BH_ * L_ * D_];

__device__ __forceinline__ float warp_sum(float s) {
#pragma unroll
    for (int o = 16; o > 0; o >>= 1) s += __shfl_xor_sync(0xffffffffu, s, o);
    return s;
}
__device__ __forceinline__ float warp_max(float s) {
#pragma unroll
    for (int o = 16; o > 0; o >>= 1) s = fmaxf(s, __shfl_xor_sync(0xffffffffu, s, o));
    return s;
}

__device__ __forceinline__ void ldsm4(u32 addr, u32* r) {
    asm volatile("ldmatrix.sync.aligned.m8n8.x4.shared.b16 {%0,%1,%2,%3}, [%4];"
                 : "=r"(r[0]), "=r"(r[1]), "=r"(r[2]), "=r"(r[3]) : "r"(addr));
}
__device__ __forceinline__ void ldsm4t(u32 addr, u32* r) {
    asm volatile("ldmatrix.sync.aligned.m8n8.x4.trans.shared.b16 {%0,%1,%2,%3}, [%4];"
                 : "=r"(r[0]), "=r"(r[1]), "=r"(r[2]), "=r"(r[3]) : "r"(addr));
}
__device__ __forceinline__ void hmma(float* c, const u32* a, u32 b0, u32 b1) {
    asm volatile(
        "mma.sync.aligned.m16n8k16.row.col.f32.f16.f16.f32 "
        "{%0,%1,%2,%3}, {%4,%5,%6,%7}, {%8,%9}, {%0,%1,%2,%3};"
        : "+f"(c[0]), "+f"(c[1]), "+f"(c[2]), "+f"(c[3])
        : "r"(a[0]), "r"(a[1]), "r"(a[2]), "r"(a[3]), "r"(b0), "r"(b1));
}
__device__ __forceinline__ void cpa16(u32 dst, const void* src) {
    asm volatile("cp.async.cg.shared.global [%0], [%1], 16;" :: "r"(dst), "l"(src));
}
__device__ __forceinline__ void cpa_commit() {
    asm volatile("cp.async.commit_group;");
}

__global__ void prep_kernel(const float* __restrict__ q,
                            const float* __restrict__ k,
                            const float* __restrict__ v) {
    const int warp = (blockIdx.x * blockDim.x + threadIdx.x) >> 5;
    const int lane = threadIdx.x & 31;
    const int b = warp / (L_ * H_);
    const int rem = warp % (L_ * H_);
    const int l = rem / H_;
    const int h = rem % H_;
    const long src = (((long)b * L_ + l) * H_ + h) * D_ + 2 * lane;
    const long dst = (((long)b * H_ + h) * L_ + l) * D_ + 2 * lane;

    float2 qv = *(const float2*)(q + src);
    float s = warp_sum(qv.x * qv.x + qv.y * qv.y);
    float sc = 1.0f / fmaxf(sqrtf(s), 1e-8f);
    *(half2*)(g_qh + dst) = __floats2half2_rn(qv.x * sc, qv.y * sc);

    float2 kv = *(const float2*)(k + src);
    s = warp_sum(kv.x * kv.x + kv.y * kv.y);
    sc = 1.0f / fmaxf(sqrtf(s), 1e-8f);
    *(half2*)(g_kh + dst) = __floats2half2_rn(kv.x * sc, kv.y * sc);

    float2 vv = *(const float2*)(v + src);
    *(half2*)(g_vh + dst) = __floats2half2_rn(vv.x, vv.y);
}

// SMEM: sP  f16[32][1024] @0      (65536B) 16B-chunk swizzle ch^(row&7), row stride 2048B
//       sQ  f16[32][64]   @65536  ( 4096B)
//       sKV double buffer @69632 / @86016 (16384B each, f16[128][64] swizzled)
#define SP_OFF   0
#define SQ_OFF   65536
#define SKV0_OFF 69632
#define SKV1_OFF 86016
#define SMEM_BYTES 102400

// async-load one 128x64 f16 tile into swizzled buffer
__device__ __forceinline__ void tile_load_async(u32 dstu, const __half* src, int t) {
#pragma unroll
    for (int i = 0; i < 4; i++) {
        const int idx = t + 256 * i;
        const int row = idx >> 3;
        const int ch = idx & 7;
        cpa16(dstu + (((row << 3) | (ch ^ (row & 7))) << 4), src + idx * 8);
    }
}

__global__ __launch_bounds__(256, 2)
void attn_kernel(float* __restrict__ outp, float* __restrict__ attnp) {
    extern __shared__ char smem[];
    const u32 sbase = (u32)__cvta_generic_to_shared(smem);
    const u32 sPu = sbase + SP_OFF;
    const u32 sQu = sbase + SQ_OFF;
    const u32 skv[2] = {sbase + SKV0_OFF, sbase + SKV1_OFF};

    const int t = threadIdx.x;
    const int tx = t & 31;
    const int ty = t >> 5;
    const int wm = ty & 1;
    const int wn = ty >> 1;
    const int bh = blockIdx.y;
    const int q0 = blockIdx.x * TM;
    const int lg = tx >> 2;
    const int ltg = tx & 3;
    const int lm = tx >> 3;
    const int lr = tx & 7;

    const __half* Qg = g_qh + ((long)bh * L_ + q0) * D_;
    const __half* Kg = g_kh + (long)bh * L_ * D_;
    const __half* Vg = g_vh + (long)bh * L_ * D_;

    u32 fa[4];
    u32 fb[4];

    // ---- Q tile (32x64 f16) swizzled, synchronous ----
    {
        const uint4* src = (const uint4*)Qg;
        uint4* dst = (uint4*)(smem + SQ_OFF);
        const int row = t >> 3;
        const int ch = t & 7;
        dst[(row << 3) | (ch ^ (row & 7))] = src[t];
    }

    // prefetch K tile 0
    tile_load_async(skv[0], Kg, t);
    cpa_commit();

    // ================ phase 1: S = Qn Kn^T * INV_TEMP -> fp16 sP ================
    for (int kt = 0; kt < 8; kt++) {
        if (kt < 7) {
            tile_load_async(skv[(kt + 1) & 1], Kg + (size_t)(kt + 1) * KC * D_, t);
        } else {
            tile_load_async(skv[0], Vg, t);   // prefetch V0, overlaps softmax
        }
        cpa_commit();
        asm volatile("cp.async.wait_group 1;");
        __syncthreads();

        const u32 sKVu = skv[kt & 1];
        float c[4][4];
#pragma unroll
        for (int nt = 0; nt < 4; nt++) {
            c[nt][0] = 0.0f; c[nt][1] = 0.0f; c[nt][2] = 0.0f; c[nt][3] = 0.0f;
        }
#pragma unroll
        for (int kk = 0; kk < 4; kk++) {
            const int arow = 16 * wm + (lm & 1) * 8 + lr;
            const int ach = 2 * kk + (lm >> 1);
            ldsm4(sQu + arow * 128 + ((ach ^ (arow & 7)) << 4), fa);
#pragma unroll
            for (int p = 0; p < 2; p++) {
                const int brow = wn * 32 + p * 16 + (lm >> 1) * 8 + lr;
                const int bch = 2 * kk + (lm & 1);
                ldsm4(sKVu + brow * 128 + ((bch ^ (brow & 7)) << 4), fb);
                hmma(c[2 * p], fa, fb[0], fb[1]);
                hmma(c[2 * p + 1], fa, fb[2], fb[3]);
            }
        }
        // store S tiles as fp16 into sP (chunk = col>>3, byte-in-chunk = (col&7)*2)
#pragma unroll
        for (int nt = 0; nt < 4; nt++) {
            const int chunk = kt * 16 + wn * 4 + nt;
            const int r0 = 16 * wm + lg;
            const int r1 = r0 + 8;
            char* p0 = smem + SP_OFF + r0 * 2048 + ((chunk ^ (r0 & 7)) << 4) + 4 * ltg;
            char* p1 = smem + SP_OFF + r1 * 2048 + ((chunk ^ (r1 & 7)) << 4) + 4 * ltg;
            *(half2*)p0 = __floats2half2_rn(c[nt][0] * INV_TEMP, c[nt][1] * INV_TEMP);
            *(half2*)p1 = __floats2half2_rn(c[nt][2] * INV_TEMP, c[nt][3] * INV_TEMP);
        }
        __syncthreads();
    }

    // ====== phase 2: softmax on fp16 s -> fp32 attn gmem + fp16 P in place ======
#pragma unroll
    for (int rr = 0; rr < 4; rr++) {
        const int row = ty * 4 + rr;
        char* rowp = smem + SP_OFF + row * 2048;
        float4* arow4 = (float4*)(attnp + ((long)bh * L_ + q0 + row) * L_);

        float vals[32];
        float m = -1e30f;
#pragma unroll
        for (int i = 0; i < 4; i++) {
            const uint4 raw = *(uint4*)(rowp + (((tx + 32 * i) ^ (row & 7)) << 4));
            const u32 rw[4] = {raw.x, raw.y, raw.z, raw.w};
#pragma unroll
            for (int j = 0; j < 4; j++) {
                float2 f2 = __half22float2(*(const half2*)&rw[j]);
                vals[i * 8 + 2 * j]     = f2.x;
                vals[i * 8 + 2 * j + 1] = f2.y;
                m = fmaxf(m, fmaxf(f2.x, f2.y));
            }
        }
        m = warp_max(m);
        float ssum = 0.0f;
#pragma unroll
        for (int i = 0; i < 32; i++) {
            vals[i] = __expf(vals[i] - m);
            ssum += vals[i];
        }
        ssum = warp_sum(ssum);
        const float inv = 1.0f / ssum;

#pragma unroll
        for (int i = 0; i < 4; i++) {
            const int cbase = (tx + 32 * i) * 8;
#pragma unroll
            for (int j = 0; j < 8; j++) vals[i * 8 + j] *= inv;
            float4 w0 = make_float4(vals[i * 8 + 0], vals[i * 8 + 1], vals[i * 8 + 2], vals[i * 8 + 3]);
            float4 w1 = make_float4(vals[i * 8 + 4], vals[i * 8 + 5], vals[i * 8 + 6], vals[i * 8 + 7]);
            arow4[cbase / 4]     = w0;
            arow4[cbase / 4 + 1] = w1;
            uint4 pk;
            *(half2*)&pk.x = __floats2half2_rn(w0.x, w0.y);
            *(half2*)&pk.y = __floats2half2_rn(w0.z, w0.w);
            *(half2*)&pk.z = __floats2half2_rn(w1.x, w1.y);
            *(half2*)&pk.w = __floats2half2_rn(w1.z, w1.w);
            *(uint4*)(rowp + (((tx + 32 * i) ^ (row & 7)) << 4)) = pk;
        }
    }
    __syncthreads();

    // ================= phase 3: O = P @ V =================
    float oc0[4];
    float oc1[4];
    oc0[0] = oc0[1] = oc0[2] = oc0[3] = 0.0f;
    oc1[0] = oc1[1] = oc1[2] = oc1[3] = 0.0f;

    for (int vc = 0; vc < 8; vc++) {
        if (vc < 7) {
            tile_load_async(skv[(vc + 1) & 1], Vg + (size_t)(vc + 1) * KC * D_, t);
            cpa_commit();
            asm volatile("cp.async.wait_group 1;");
        } else {
            asm volatile("cp.async.wait_group 0;");
        }
        __syncthreads();

        const u32 sKVu = skv[vc & 1];
#pragma unroll
        for (int kk = 0; kk < 8; kk++) {
            const int arow = 16 * wm + (lm & 1) * 8 + lr;
            const int ach = vc * 16 + 2 * kk + (lm >> 1);
            ldsm4(sPu + arow * 2048 + ((ach ^ (arow & 7)) << 4), fa);

            const int srow = kk * 16 + (lm & 1) * 8 + lr;
            const int sch = wn * 2 + (lm >> 1);
            ldsm4t(sKVu + srow * 128 + ((sch ^ (srow & 7)) << 4), fb);

            hmma(oc0, fa, fb[0], fb[1]);
            hmma(oc1, fa, fb[2], fb[3]);
        }
        if (vc < 7) __syncthreads();
    }

    // ---- epilogue ----
    {
        const int d0 = wn * 16 + 2 * ltg;
        const long base0 = ((long)bh * L_ + q0 + 16 * wm + lg) * D_ + d0;
        *(float2*)(outp + base0)           = make_float2(oc0[0], oc0[1]);
        *(float2*)(outp + base0 + 8 * D_)  = make_float2(oc0[2], oc0[3]);
        const long base1 = base0 + 8;
        *(float2*)(outp + base1)           = make_float2(oc1[0], oc1[1]);
        *(float2*)(outp + base1 + 8 * D_)  = make_float2(oc1[2], oc1[3]);
    }
}

extern "C" void kernel_launch(void* const* d_in, const int* in_sizes, int n_in,
                              void* d_out, int out_size) {
    const float* q = (const float*)d_in[0];
    const float* k = (const float*)d_in[1];
    const float* v = (const float*)d_in[2];
    float* outp  = (float*)d_out;
    float* attnp = outp + (long)BH_ * L_ * D_;

    prep_kernel<<<(B_ * L_ * H_) / 8, 256>>>(q, k, v);

    cudaFuncSetAttribute(attn_kernel, cudaFuncAttributeMaxDynamicSharedMemorySize,
                         SMEM_BYTES);
    dim3 grid(L_ / TM, BH_);
    attn_kernel<<<grid, 256, SMEM_BYTES>>>(outp, attnp);
}

// round 7
// speedup vs baseline: 5.4779x; 1.3506x over previous
#include <cuda_runtime.h>
#include <cuda_fp16.h>
#include <stdint.h>
#include <math.h>

#define B_ 4
#define L_ 1024
#define H_ 8
#define D_ 64
#define BH_ 32
#define INV_TEMP 0.125f
#define KC 128

typedef unsigned int u32;

__device__ __align__(16) __half g_qh[BH_ * L_ * D_];
__device__ __align__(16) __half g_kh[BH_ * L_ * D_];
__device__ __align__(16) __half g_vh[BH_ * L_ * D_];

__device__ __forceinline__ void ldsm4(u32 addr, u32* r) {
    asm volatile("ldmatrix.sync.aligned.m8n8.x4.shared.b16 {%0,%1,%2,%3}, [%4];"
                 : "=r"(r[0]), "=r"(r[1]), "=r"(r[2]), "=r"(r[3]) : "r"(addr));
}
__device__ __forceinline__ void ldsm4t(u32 addr, u32* r) {
    asm volatile("ldmatrix.sync.aligned.m8n8.x4.trans.shared.b16 {%0,%1,%2,%3}, [%4];"
                 : "=r"(r[0]), "=r"(r[1]), "=r"(r[2]), "=r"(r[3]) : "r"(addr));
}
__device__ __forceinline__ void hmma(float* c, const u32* a, u32 b0, u32 b1) {
    asm volatile(
        "mma.sync.aligned.m16n8k16.row.col.f32.f16.f16.f32 "
        "{%0,%1,%2,%3}, {%4,%5,%6,%7}, {%8,%9}, {%0,%1,%2,%3};"
        : "+f"(c[0]), "+f"(c[1]), "+f"(c[2]), "+f"(c[3])
        : "r"(a[0]), "r"(a[1]), "r"(a[2]), "r"(a[3]), "r"(b0), "r"(b1));
}
__device__ __forceinline__ void cpa16(u32 dst, const void* src) {
    asm volatile("cp.async.cg.shared.global [%0], [%1], 16;" :: "r"(dst), "l"(src));
}
#define CPA_COMMIT() asm volatile("cp.async.commit_group;")
#define CPA_WAIT(n)  asm volatile("cp.async.wait_group " #n ";")

__device__ __forceinline__ u32 pack_h2(float a, float b) {
    half2 h = __floats2half2_rn(a, b);
    return *(u32*)&h;
}

// ---- prep: 2 rows per warp, float4 lanes; L2-normalize q,k; copy v ----
__global__ void prep_kernel(const float* __restrict__ q,
                            const float* __restrict__ k,
                            const float* __restrict__ v) {
    const int gw = (blockIdx.x * blockDim.x + threadIdx.x) >> 5;
    const int lane = threadIdx.x & 31;
    const int r = gw * 2 + (lane >> 4);
    const int c4 = lane & 15;
    const int b = r / (L_ * H_);
    const int rem = r % (L_ * H_);
    const int l = rem / H_;
    const int h = rem % H_;
    const long src = (((long)b * L_ + l) * H_ + h) * D_ + c4 * 4;
    const long dst = (((long)b * H_ + h) * L_ + l) * D_ + c4 * 4;

    float4 qv = *(const float4*)(q + src);
    float ss = qv.x * qv.x + qv.y * qv.y + qv.z * qv.z + qv.w * qv.w;
#pragma unroll
    for (int o = 1; o < 16; o <<= 1) ss += __shfl_xor_sync(0xffffffffu, ss, o);
    float sc = 1.0f / fmaxf(sqrtf(ss), 1e-8f);
    uint2 pk;
    pk.x = pack_h2(qv.x * sc, qv.y * sc);
    pk.y = pack_h2(qv.z * sc, qv.w * sc);
    *(uint2*)(g_qh + dst) = pk;

    float4 kv = *(const float4*)(k + src);
    ss = kv.x * kv.x + kv.y * kv.y + kv.z * kv.z + kv.w * kv.w;
#pragma unroll
    for (int o = 1; o < 16; o <<= 1) ss += __shfl_xor_sync(0xffffffffu, ss, o);
    sc = 1.0f / fmaxf(sqrtf(ss), 1e-8f);
    pk.x = pack_h2(kv.x * sc, kv.y * sc);
    pk.y = pack_h2(kv.z * sc, kv.w * sc);
    *(uint2*)(g_kh + dst) = pk;

    float4 vv = *(const float4*)(v + src);
    pk.x = pack_h2(vv.x, vv.y);
    pk.y = pack_h2(vv.z, vv.w);
    *(uint2*)(g_vh + dst) = pk;
}

// SMEM map:
//   sQ   @0      4096B   (f16 32x64 swizzled)
//   sRed @4096    512B   (f32 [32 rows][4 wn] softmax sums)
//   sKV  @5120   3x16384 (cp.async ring, f16 128x64 swizzled)
//   red  @5120   aliased (f32 O-reduce, 8 bufs x16 rows x68 stride = 34816B)
#define SQ_OFF   0
#define SRED_OFF 4096
#define SKV_OFF  5120
#define RED_OFF  5120
#define RED_STRIDE 68
#define SMEM_BYTES (5120 + 3 * 16384)

__device__ __forceinline__ void tile_load_async(u32 dstu, const __half* src, int t) {
#pragma unroll
    for (int i = 0; i < 4; i++) {
        const int idx = t + 256 * i;
        const int row = idx >> 3;
        const int ch = idx & 7;
        cpa16(dstu + (((row << 3) | (ch ^ (row & 7))) << 4), src + idx * 8);
    }
}

__global__ __launch_bounds__(256, 2)
void attn_kernel(float* __restrict__ outp, float* __restrict__ attnp) {
    extern __shared__ char smem[];
    const u32 sbase = (u32)__cvta_generic_to_shared(smem);
    const u32 sQu = sbase + SQ_OFF;
    const u32 skv0 = sbase + SKV_OFF;
    float* sRed = (float*)(smem + SRED_OFF);
    float* red = (float*)(smem + RED_OFF);

    const int t = threadIdx.x;
    const int tx = t & 31;
    const int ty = t >> 5;
    const int wm = ty & 1;       // m16 group
    const int wn = ty >> 1;      // warp column 0..3 (n/k slice)
    const int bh = blockIdx.y;
    const int q0 = blockIdx.x * 32;
    const int lg = tx >> 2;
    const int ltg = tx & 3;
    const int lm = tx >> 3;
    const int lr = tx & 7;

    const __half* Qg = g_qh + ((long)bh * L_ + q0) * D_;
    const __half* Kg = g_kh + (long)bh * L_ * D_;
    const __half* Vg = g_vh + (long)bh * L_ * D_;

    u32 ph[64];        // S/P fragments: m16 x n256 per warp (half2)
    u32 qf[4][4];      // Q A-fragments, k64
    u32 fb[4];

    // Q tile -> SMEM (swizzled)
    {
        const uint4* src = (const uint4*)Qg;
        uint4* dst = (uint4*)(smem + SQ_OFF);
        const int row = t >> 3;
        const int ch = t & 7;
        dst[(row << 3) | (ch ^ (row & 7))] = src[t];
    }

    // prefetch tiles 0,1 (K0, K1)
    tile_load_async(skv0, Kg, t);
    CPA_COMMIT();
    tile_load_async(skv0 + 16384, Kg + KC * D_, t);
    CPA_COMMIT();

    // ================= phase 1: S fragments in registers =================
#pragma unroll
    for (int kt = 0; kt < 8; kt++) {
        CPA_WAIT(1);
        __syncthreads();
        if (kt == 0) {
            // hoist Q fragments
#pragma unroll
            for (int kk = 0; kk < 4; kk++) {
                const int arow = 16 * wm + (lm & 1) * 8 + lr;
                const int ach = 2 * kk + (lm >> 1);
                ldsm4(sQu + arow * 128 + ((ach ^ (arow & 7)) << 4), qf[kk]);
            }
        }
        // prefetch tile kt+2 (K for kt<6, V0 at kt==6, V1 at kt==7)
        {
            const __half* src = (kt < 6) ? (Kg + (size_t)(kt + 2) * KC * D_)
                                         : (Vg + (size_t)(kt - 6) * KC * D_);
            tile_load_async(skv0 + ((kt + 2) % 3) * 16384, src, t);
            CPA_COMMIT();
        }

        const u32 sKVu = skv0 + (kt % 3) * 16384;
        float c[4][4];
#pragma unroll
        for (int nt = 0; nt < 4; nt++) {
            c[nt][0] = 0.0f; c[nt][1] = 0.0f; c[nt][2] = 0.0f; c[nt][3] = 0.0f;
        }
#pragma unroll
        for (int kk = 0; kk < 4; kk++) {
#pragma unroll
            for (int p = 0; p < 2; p++) {
                const int brow = wn * 32 + p * 16 + (lm >> 1) * 8 + lr;
                const int bch = 2 * kk + (lm & 1);
                ldsm4(sKVu + brow * 128 + ((bch ^ (brow & 7)) << 4), fb);
                hmma(c[2 * p], qf[kk], fb[0], fb[1]);
                hmma(c[2 * p + 1], qf[kk], fb[2], fb[3]);
            }
        }
        // pack scaled logits into A-fragment order
#pragma unroll
        for (int pair = 0; pair < 2; pair++) {
            ph[kt * 8 + pair * 4 + 0] = pack_h2(c[2 * pair][0] * INV_TEMP, c[2 * pair][1] * INV_TEMP);
            ph[kt * 8 + pair * 4 + 1] = pack_h2(c[2 * pair][2] * INV_TEMP, c[2 * pair][3] * INV_TEMP);
            ph[kt * 8 + pair * 4 + 2] = pack_h2(c[2 * pair + 1][0] * INV_TEMP, c[2 * pair + 1][1] * INV_TEMP);
            ph[kt * 8 + pair * 4 + 3] = pack_h2(c[2 * pair + 1][2] * INV_TEMP, c[2 * pair + 1][3] * INV_TEMP);
        }
    }

    // ================= softmax (no max shift; |logit| <= 0.125) =================
    float slo = 0.0f, shi = 0.0f;
#pragma unroll
    for (int i = 0; i < 64; i++) {
        float2 f = __half22float2(*(half2*)&ph[i]);
        float e0 = __expf(f.x);
        float e1 = __expf(f.y);
        if ((i & 1) == 0) slo += e0 + e1; else shi += e0 + e1;
        ph[i] = pack_h2(e0, e1);
    }
    slo += __shfl_xor_sync(0xffffffffu, slo, 1);
    slo += __shfl_xor_sync(0xffffffffu, slo, 2);
    shi += __shfl_xor_sync(0xffffffffu, shi, 1);
    shi += __shfl_xor_sync(0xffffffffu, shi, 2);
    if (ltg == 0) {
        sRed[(16 * wm + lg) * 4 + wn] = slo;
        sRed[(16 * wm + lg + 8) * 4 + wn] = shi;
    }
    __syncthreads();
    float inv_lo, inv_hi;
    {
        const int rlo = 16 * wm + lg;
        inv_lo = 1.0f / (sRed[rlo * 4] + sRed[rlo * 4 + 1] + sRed[rlo * 4 + 2] + sRed[rlo * 4 + 3]);
        inv_hi = 1.0f / (sRed[(rlo + 8) * 4] + sRed[(rlo + 8) * 4 + 1] +
                         sRed[(rlo + 8) * 4 + 2] + sRed[(rlo + 8) * 4 + 3]);
    }

    // normalize: write attn (streaming) + repack normalized fp16 P
    {
        float* row_lo = attnp + ((long)(bh * L_ + q0 + 16 * wm + lg)) * L_;
        float* row_hi = row_lo + 8 * L_;
#pragma unroll
        for (int i = 0; i < 64; i++) {
            const int col = (i >> 3) * 128 + wn * 32 + ((i >> 2) & 1) * 16 + ((i >> 1) & 1) * 8 + 2 * ltg;
            float2 e = __half22float2(*(half2*)&ph[i]);
            const float inv = (i & 1) ? inv_hi : inv_lo;
            float2 w = make_float2(e.x * inv, e.y * inv);
            __stcs((float2*)(((i & 1) ? row_hi : row_lo) + col), w);
            ph[i] = pack_h2(w.x, w.y);
        }
    }

    // ================= phase 3: O partials = P(k-slice) @ V =================
    float oc[8][4];
#pragma unroll
    for (int d = 0; d < 8; d++) {
        oc[d][0] = 0.0f; oc[d][1] = 0.0f; oc[d][2] = 0.0f; oc[d][3] = 0.0f;
    }

#pragma unroll
    for (int vc = 0; vc < 8; vc++) {
        if (vc == 7) { CPA_WAIT(0); } else { CPA_WAIT(1); }
        __syncthreads();
        if (vc < 6) {
            tile_load_async(skv0 + ((vc + 4) % 3) * 16384, Vg + (size_t)(vc + 2) * KC * D_, t);
            CPA_COMMIT();
        }
        const u32 sVu = skv0 + ((vc + 2) % 3) * 16384;
#pragma unroll
        for (int pair = 0; pair < 2; pair++) {
            const u32* aP = &ph[vc * 8 + pair * 4];
            const int srow = wn * 32 + pair * 16 + (lm & 1) * 8 + lr;
#pragma unroll
            for (int db = 0; db < 4; db++) {
                const int sch = 2 * db + (lm >> 1);
                ldsm4t(sVu + srow * 128 + ((sch ^ (srow & 7)) << 4), fb);
                hmma(oc[2 * db], aP, fb[0], fb[1]);
                hmma(oc[2 * db + 1], aP, fb[2], fb[3]);
            }
        }
    }

    // ================= O reduction across warp columns =================
    __syncthreads();   // all MMA reads done before aliasing red over sKV
    {
        const int buf = (wm * 4 + wn) * 16;
#pragma unroll
        for (int t8 = 0; t8 < 8; t8++) {
            *(float2*)&red[(buf + lg) * RED_STRIDE + t8 * 8 + 2 * ltg] =
                make_float2(oc[t8][0], oc[t8][1]);
            *(float2*)&red[(buf + lg + 8) * RED_STRIDE + t8 * 8 + 2 * ltg] =
                make_float2(oc[t8][2], oc[t8][3]);
        }
    }
    __syncthreads();
    {
        const int r = t >> 3;         // output row 0..31
        const int seg = t & 7;        // 8-float segment
        float acc[8];
#pragma unroll
        for (int j = 0; j < 8; j++) acc[j] = 0.0f;
#pragma unroll
        for (int w = 0; w < 4; w++) {
            const float* src = &red[(((r >> 4) * 4 + w) * 16 + (r & 15)) * RED_STRIDE + seg * 8];
#pragma unroll
            for (int j = 0; j < 8; j++) acc[j] += src[j];
        }
        float* dst = outp + ((long)(bh * L_ + q0 + r)) * D_ + seg * 8;
        *(float4*)dst = make_float4(acc[0], acc[1], acc[2], acc[3]);
        *(float4*)(dst + 4) = make_float4(acc[4], acc[5], acc[6], acc[7]);
    }
}

extern "C" void kernel_launch(void* const* d_in, const int* in_sizes, int n_in,
                              void* d_out, int out_size) {
    const float* q = (const float*)d_in[0];
    const float* k = (const float*)d_in[1];
    const float* v = (const float*)d_in[2];
    float* outp  = (float*)d_out;
    float* attnp = outp + (long)BH_ * L_ * D_;

    // 32768 rows, 16 rows per 256-thread CTA
    prep_kernel<<<2048, 256>>>(q, k, v);

    cudaFuncSetAttribute(attn_kernel, cudaFuncAttributeMaxDynamicSharedMemorySize,
                         SMEM_BYTES);
    dim3 grid(L_ / 32, BH_);
    attn_kernel<<<grid, 256, SMEM_BYTES>>>(outp, attnp);
}